// round 12
// baseline (speedup 1.0000x reference)
#include <cuda_runtime.h>
#include <cuda_bf16.h>
#include <math.h>

// Problem constants
#define BB 4
#define SS 1024
#define DD 1024
#define HH 16
#define DHH 64
#define MSZ (BB * SS)  // 4096 rows

// Scratch (no cudaMalloc allowed)
__device__ float g_Q[(size_t)MSZ * DD];
__device__ float g_K[(size_t)MSZ * DD];
__device__ float g_V[(size_t)MSZ * DD];
__device__ float g_C[(size_t)MSZ * DD];
__device__ unsigned char g_mask[BB * SS];

// ----------------------------------------------------------------------------
// Mask canonicalization (verified R4)
// ----------------------------------------------------------------------------
__global__ __launch_bounds__(1024) void mask_prep_kernel(
    const unsigned char* __restrict__ m0,
    const unsigned char* __restrict__ m1)
{
    __shared__ int s_flags;
    const int t = threadIdx.x;
    if (t == 0) s_flags = 0;
    __syncthreads();

    int f1 = 0, f23 = 0;
    for (int i = t; i < BB * SS; i += 1024) {
        unsigned char a = (unsigned char)(m0[i] | m1[i]);
        int r = i & 3;
        if (a) {
            if (r == 1) f1 = 1;
            else if (r >= 2) f23 = 1;
        }
    }
    if (f1)  atomicOr(&s_flags, 1);
    if (f23) atomicOr(&s_flags, 2);
    __syncthreads();

    const int fl = s_flags;
    int code;
    if (fl & 1)      code = 0;  // uint8
    else if (fl & 2) code = 1;  // float32
    else             code = 2;  // int32

    for (int i = t; i < BB * SS; i += 1024) {
        unsigned char mm;
        if (code == 0) {
            mm = (unsigned char)((m0[i] != 0) | (m1[i] != 0));
        } else if (code == 1) {
            mm = (unsigned char)((((const float*)m0)[i] != 0.f) |
                                 (((const float*)m1)[i] != 0.f));
        } else {
            mm = (unsigned char)((((const int*)m0)[i] != 0) |
                                 (((const int*)m1)[i] != 0));
        }
        g_mask[i] = mm;
    }
}

// ----------------------------------------------------------------------------
// Shared helpers
// ----------------------------------------------------------------------------
__device__ __forceinline__ void mma16816(
    float& c0, float& c1, float& c2, float& c3,
    unsigned a0, unsigned a1, unsigned a2, unsigned a3,
    unsigned b0, unsigned b1)
{
    asm volatile(
        "mma.sync.aligned.m16n8k16.row.col.f32.bf16.bf16.f32 "
        "{%0,%1,%2,%3}, {%4,%5,%6,%7}, {%8,%9}, {%0,%1,%2,%3};\n"
        : "+f"(c0), "+f"(c1), "+f"(c2), "+f"(c3)
        : "r"(a0), "r"(a1), "r"(a2), "r"(a3), "r"(b0), "r"(b1));
}

__device__ __forceinline__ void ldsm4(unsigned addr, unsigned& r0, unsigned& r1,
                                      unsigned& r2, unsigned& r3)
{
    asm volatile(
        "ldmatrix.sync.aligned.m8n8.x4.shared.b16 {%0,%1,%2,%3}, [%4];"
        : "=r"(r0), "=r"(r1), "=r"(r2), "=r"(r3) : "r"(addr));
}

__device__ __forceinline__ void split2(float x, float y, unsigned& h, unsigned& l)
{
    __nv_bfloat16 hx = __float2bfloat16(x);
    __nv_bfloat16 hy = __float2bfloat16(y);
    __nv_bfloat16 lx = __float2bfloat16(x - __bfloat162float(hx));
    __nv_bfloat16 ly = __float2bfloat16(y - __bfloat162float(hy));
    __nv_bfloat162 hh; hh.x = hx; hh.y = hy;
    __nv_bfloat162 ll; ll.x = lx; ll.y = ly;
    h = *(unsigned*)&hh;
    l = *(unsigned*)&ll;
}

__device__ __forceinline__ void split1(float x, __nv_bfloat16& h, __nv_bfloat16& l)
{
    h = __float2bfloat16(x);
    l = __float2bfloat16(x - __bfloat162float(h));
}

// ----------------------------------------------------------------------------
// Tensor-core GEMM (R9 base + pass-reordered MMA issue to break acc chains).
// C[M,N] = A[M,K] @ W[N,K]^T + bias[N]
// ----------------------------------------------------------------------------
#define SM_STRIDE 40
#define GPLANE    (128 * SM_STRIDE)
#define PLB       (GPLANE * 2)
#define STAGEB    (4 * PLB)
#define GSMEM     (2 * STAGEB)

__global__ __launch_bounds__(256, 2) void gemm_mma_kernel(
    const float* __restrict__ A, const float* __restrict__ W,
    const float* __restrict__ bias, float* __restrict__ C,
    int M, int N, int K)
{
    extern __shared__ __nv_bfloat16 smdyn[];

    const int tid  = threadIdx.x;
    const int bm   = blockIdx.y * 128;
    const int bn   = blockIdx.x * 128;
    const int wid  = tid >> 5;
    const int lane = tid & 31;
    const int wm   = wid & 1;
    const int wn   = wid >> 1;
    const int g    = lane >> 2;
    const int tg   = lane & 3;

    const int lm = lane >> 3;
    const int lt = lane & 7;
    unsigned smem_u32;
    {
        unsigned long long p = __cvta_generic_to_shared(smdyn);
        smem_u32 = (unsigned)p;
    }
    const unsigned aoff = ((wm * 64 + ((lm & 1) << 3) + lt) * SM_STRIDE +
                           ((lm >> 1) << 3)) * 2;
    const unsigned boff = ((wn * 32 + ((lm >> 1) << 3) + lt) * SM_STRIDE +
                           ((lm & 1) << 3)) * 2;

    float acc[4][4][4];
#pragma unroll
    for (int mt = 0; mt < 4; mt++)
#pragma unroll
        for (int nt = 0; nt < 4; nt++)
#pragma unroll
            for (int e = 0; e < 4; e++) acc[mt][nt][e] = 0.f;

    const int srow = tid >> 3;
    const int sc4  = (tid & 7) << 2;

    float4 av[4], wv[4];
#pragma unroll
    for (int i = 0; i < 4; i++) {
        int row = srow + i * 32;
        av[i] = *(const float4*)&A[(size_t)(bm + row) * K + sc4];
        wv[i] = *(const float4*)&W[(size_t)(bn + row) * K + sc4];
    }
    {
        __nv_bfloat16* Ahp = smdyn;
        __nv_bfloat16* Alp = smdyn + GPLANE;
        __nv_bfloat16* Whp = smdyn + 2 * GPLANE;
        __nv_bfloat16* Wlp = smdyn + 3 * GPLANE;
#pragma unroll
        for (int i = 0; i < 4; i++) {
            int row = srow + i * 32;
            float ax[4] = {av[i].x, av[i].y, av[i].z, av[i].w};
            float wx[4] = {wv[i].x, wv[i].y, wv[i].z, wv[i].w};
#pragma unroll
            for (int e = 0; e < 4; e++) {
                __nv_bfloat16 h, l;
                split1(ax[e], h, l);
                Ahp[row * SM_STRIDE + sc4 + e] = h;
                Alp[row * SM_STRIDE + sc4 + e] = l;
                split1(wx[e], h, l);
                Whp[row * SM_STRIDE + sc4 + e] = h;
                Wlp[row * SM_STRIDE + sc4 + e] = l;
            }
        }
    }
    __syncthreads();

    const int NT = K / 32;
    for (int kt = 0; kt < NT; kt++) {
        const int cur = kt & 1;
        if (kt + 1 < NT) {
            int k0 = (kt + 1) * 32;
#pragma unroll
            for (int i = 0; i < 4; i++) {
                int row = srow + i * 32;
                av[i] = *(const float4*)&A[(size_t)(bm + row) * K + k0 + sc4];
                wv[i] = *(const float4*)&W[(size_t)(bn + row) * K + k0 + sc4];
            }
        }

        const unsigned sbase = smem_u32 + (unsigned)cur * STAGEB;
#pragma unroll
        for (int ks = 0; ks < 32; ks += 16) {
            unsigned bh[4][2], bl[4][2];
#pragma unroll
            for (int p = 0; p < 2; p++) {
                unsigned ad = sbase + 2 * PLB + boff +
                              (unsigned)(p * 16 * SM_STRIDE + ks) * 2;
                unsigned r0, r1, r2, r3;
                ldsm4(ad, r0, r1, r2, r3);
                bh[2 * p][0] = r0; bh[2 * p][1] = r1;
                bh[2 * p + 1][0] = r2; bh[2 * p + 1][1] = r3;
                ldsm4(ad + PLB, r0, r1, r2, r3);
                bl[2 * p][0] = r0; bl[2 * p][1] = r1;
                bl[2 * p + 1][0] = r2; bl[2 * p + 1][1] = r3;
            }
#pragma unroll
            for (int mh = 0; mh < 2; mh++) {
                unsigned ah[2][4], al[2][4];
#pragma unroll
                for (int m2 = 0; m2 < 2; m2++) {
                    int mt = mh * 2 + m2;
                    unsigned ad = sbase + aoff +
                                  (unsigned)(mt * 16 * SM_STRIDE + ks) * 2;
                    ldsm4(ad, ah[m2][0], ah[m2][1], ah[m2][2], ah[m2][3]);
                    ldsm4(ad + PLB, al[m2][0], al[m2][1], al[m2][2], al[m2][3]);
                }
                // pass 0: Ah x Bh (8 independent MMAs)
#pragma unroll
                for (int m2 = 0; m2 < 2; m2++) {
                    float (&a4)[4][4] = acc[mh * 2 + m2];
#pragma unroll
                    for (int nt = 0; nt < 4; nt++)
                        mma16816(a4[nt][0], a4[nt][1], a4[nt][2], a4[nt][3],
                                 ah[m2][0], ah[m2][1], ah[m2][2], ah[m2][3],
                                 bh[nt][0], bh[nt][1]);
                }
                // pass 1: Ah x Bl
#pragma unroll
                for (int m2 = 0; m2 < 2; m2++) {
                    float (&a4)[4][4] = acc[mh * 2 + m2];
#pragma unroll
                    for (int nt = 0; nt < 4; nt++)
                        mma16816(a4[nt][0], a4[nt][1], a4[nt][2], a4[nt][3],
                                 ah[m2][0], ah[m2][1], ah[m2][2], ah[m2][3],
                                 bl[nt][0], bl[nt][1]);
                }
                // pass 2: Al x Bh
#pragma unroll
                for (int m2 = 0; m2 < 2; m2++) {
                    float (&a4)[4][4] = acc[mh * 2 + m2];
#pragma unroll
                    for (int nt = 0; nt < 4; nt++)
                        mma16816(a4[nt][0], a4[nt][1], a4[nt][2], a4[nt][3],
                                 al[m2][0], al[m2][1], al[m2][2], al[m2][3],
                                 bh[nt][0], bh[nt][1]);
                }
            }
        }

        if (kt + 1 < NT) {
            int nxt = cur ^ 1;
            __syncthreads();  // all fragment reads of stage nxt (2 tiles ago) done
            __nv_bfloat16* Ahp = smdyn + nxt * 4 * GPLANE;
            __nv_bfloat16* Alp = Ahp + GPLANE;
            __nv_bfloat16* Whp = Ahp + 2 * GPLANE;
            __nv_bfloat16* Wlp = Ahp + 3 * GPLANE;
#pragma unroll
            for (int i = 0; i < 4; i++) {
                int row = srow + i * 32;
                float ax[4] = {av[i].x, av[i].y, av[i].z, av[i].w};
                float wx[4] = {wv[i].x, wv[i].y, wv[i].z, wv[i].w};
#pragma unroll
                for (int e = 0; e < 4; e++) {
                    __nv_bfloat16 h, l;
                    split1(ax[e], h, l);
                    Ahp[row * SM_STRIDE + sc4 + e] = h;
                    Alp[row * SM_STRIDE + sc4 + e] = l;
                    split1(wx[e], h, l);
                    Whp[row * SM_STRIDE + sc4 + e] = h;
                    Wlp[row * SM_STRIDE + sc4 + e] = l;
                }
            }
            __syncthreads();
        }
    }

    // Epilogue
#pragma unroll
    for (int nt = 0; nt < 4; nt++) {
        int col = bn + wn * 32 + nt * 8 + tg * 2;
        float b0 = bias[col];
        float b1 = bias[col + 1];
#pragma unroll
        for (int mt = 0; mt < 4; mt++) {
            int row = bm + wm * 64 + mt * 16 + g;
            float* p0 = C + (size_t)row * N + col;
            float* p1 = C + (size_t)(row + 8) * N + col;
            p0[0] = acc[mt][nt][0] + b0;
            p0[1] = acc[mt][nt][1] + b1;
            p1[0] = acc[mt][nt][2] + b0;
            p1[1] = acc[mt][nt][3] + b1;
        }
    }
}

// ----------------------------------------------------------------------------
// Tensor-core flash attention (R8 base + pass-reordered MMA issue).
// ----------------------------------------------------------------------------
#define AST 72

__global__ __launch_bounds__(256) void attn_mma_kernel()
{
    const int tid  = threadIdx.x;
    const int wid  = tid >> 5;
    const int lane = tid & 31;
    const int g    = lane >> 2;
    const int tg   = lane & 3;
    const int qb   = blockIdx.x * 128;
    const int h    = blockIdx.y;
    const int b    = blockIdx.z;
    const int hoff = h * DHH;
    const int qrow0 = qb + wid * 16;

    __shared__ __align__(16) __nv_bfloat16 Kh[64][AST], Kl[64][AST];
    __shared__ __align__(16) __nv_bfloat16 Vth[64][AST], Vtl[64][AST];
    __shared__ unsigned char smask[64];

    unsigned qh[4][4], ql[4][4];
    {
        const float* Q0 = g_Q + (size_t)(b * SS + qrow0 + g) * DD + hoff;
        const float* Q1 = g_Q + (size_t)(b * SS + qrow0 + g + 8) * DD + hoff;
#pragma unroll
        for (int ks = 0; ks < 4; ks++) {
            int d0 = ks * 16 + tg * 2;
            float2 f0 = *(const float2*)&Q0[d0];
            float2 f1 = *(const float2*)&Q1[d0];
            float2 f2 = *(const float2*)&Q0[d0 + 8];
            float2 f3 = *(const float2*)&Q1[d0 + 8];
            split2(f0.x, f0.y, qh[ks][0], ql[ks][0]);
            split2(f1.x, f1.y, qh[ks][1], ql[ks][1]);
            split2(f2.x, f2.y, qh[ks][2], ql[ks][2]);
            split2(f3.x, f3.y, qh[ks][3], ql[ks][3]);
        }
    }

    float out[8][4];
#pragma unroll
    for (int nt = 0; nt < 8; nt++)
#pragma unroll
        for (int e = 0; e < 4; e++) out[nt][e] = 0.f;
    float m0 = -INFINITY, m1 = -INFINITY;
    float l0 = 0.f, l1 = 0.f;

    const int krow = tid >> 2;
    const int kc4  = (tid & 3) * 16;

    for (int kt = 0; kt < SS / 64; kt++) {
        float4 kv[4], vv[4];
        const float* Kg = g_K + (size_t)(b * SS + kt * 64 + krow) * DD + hoff + kc4;
        const float* Vg = g_V + (size_t)(b * SS + kt * 64 + krow) * DD + hoff + kc4;
#pragma unroll
        for (int i = 0; i < 4; i++) {
            kv[i] = *(const float4*)&Kg[i * 4];
            vv[i] = *(const float4*)&Vg[i * 4];
        }
        __syncthreads();
#pragma unroll
        for (int i = 0; i < 4; i++) {
            float kx[4] = {kv[i].x, kv[i].y, kv[i].z, kv[i].w};
            float vx[4] = {vv[i].x, vv[i].y, vv[i].z, vv[i].w};
#pragma unroll
            for (int e = 0; e < 4; e++) {
                int d = kc4 + i * 4 + e;
                __nv_bfloat16 hh, ll;
                split1(kx[e], hh, ll);
                Kh[krow][d] = hh; Kl[krow][d] = ll;
                split1(vx[e], hh, ll);
                Vth[d][krow] = hh; Vtl[d][krow] = ll;
            }
        }
        if (tid < 64) smask[tid] = g_mask[b * SS + kt * 64 + tid];
        __syncthreads();

        // ---- S = Q @ K^T, pass-reordered: ks outer, nt-groups of 4 ----
        float sacc[8][4];
#pragma unroll
        for (int nt = 0; nt < 8; nt++)
#pragma unroll
            for (int e = 0; e < 4; e++) sacc[nt][e] = 0.f;
#pragma unroll
        for (int ks = 0; ks < 4; ks++) {
            int kc = ks * 16 + tg * 2;
#pragma unroll
            for (int ng = 0; ng < 2; ng++) {
                unsigned kbh[4][2], kbl[4][2];
#pragma unroll
                for (int j = 0; j < 4; j++) {
                    int n = (ng * 4 + j) * 8 + g;
                    kbh[j][0] = *(const unsigned*)&Kh[n][kc];
                    kbh[j][1] = *(const unsigned*)&Kh[n][kc + 8];
                    kbl[j][0] = *(const unsigned*)&Kl[n][kc];
                    kbl[j][1] = *(const unsigned*)&Kl[n][kc + 8];
                }
#pragma unroll
                for (int j = 0; j < 4; j++) {
                    float (&s4)[4] = sacc[ng * 4 + j];
                    mma16816(s4[0], s4[1], s4[2], s4[3],
                             qh[ks][0], qh[ks][1], qh[ks][2], qh[ks][3],
                             kbh[j][0], kbh[j][1]);
                }
#pragma unroll
                for (int j = 0; j < 4; j++) {
                    float (&s4)[4] = sacc[ng * 4 + j];
                    mma16816(s4[0], s4[1], s4[2], s4[3],
                             qh[ks][0], qh[ks][1], qh[ks][2], qh[ks][3],
                             kbl[j][0], kbl[j][1]);
                }
#pragma unroll
                for (int j = 0; j < 4; j++) {
                    float (&s4)[4] = sacc[ng * 4 + j];
                    mma16816(s4[0], s4[1], s4[2], s4[3],
                             ql[ks][0], ql[ks][1], ql[ks][2], ql[ks][3],
                             kbh[j][0], kbh[j][1]);
                }
            }
        }

        float tmax0 = -INFINITY, tmax1 = -INFINITY;
#pragma unroll
        for (int nt = 0; nt < 8; nt++) {
            bool msk0 = smask[nt * 8 + tg * 2] != 0;
            bool msk1 = smask[nt * 8 + tg * 2 + 1] != 0;
            sacc[nt][0] = msk0 ? -1e9f : sacc[nt][0] * 0.125f;
            sacc[nt][1] = msk1 ? -1e9f : sacc[nt][1] * 0.125f;
            sacc[nt][2] = msk0 ? -1e9f : sacc[nt][2] * 0.125f;
            sacc[nt][3] = msk1 ? -1e9f : sacc[nt][3] * 0.125f;
            tmax0 = fmaxf(tmax0, fmaxf(sacc[nt][0], sacc[nt][1]));
            tmax1 = fmaxf(tmax1, fmaxf(sacc[nt][2], sacc[nt][3]));
        }
        tmax0 = fmaxf(tmax0, __shfl_xor_sync(0xffffffffu, tmax0, 1));
        tmax0 = fmaxf(tmax0, __shfl_xor_sync(0xffffffffu, tmax0, 2));
        tmax1 = fmaxf(tmax1, __shfl_xor_sync(0xffffffffu, tmax1, 1));
        tmax1 = fmaxf(tmax1, __shfl_xor_sync(0xffffffffu, tmax1, 2));

        float mn0 = fmaxf(m0, tmax0);
        float mn1 = fmaxf(m1, tmax1);
        float corr0 = __expf(m0 - mn0);
        float corr1 = __expf(m1 - mn1);
        m0 = mn0; m1 = mn1;
        l0 *= corr0; l1 *= corr1;
#pragma unroll
        for (int nt = 0; nt < 8; nt++) {
            out[nt][0] *= corr0; out[nt][1] *= corr0;
            out[nt][2] *= corr1; out[nt][3] *= corr1;
        }

        unsigned ph[4][4], pl[4][4];
#pragma unroll
        for (int ksp = 0; ksp < 4; ksp++) {
            float p00 = __expf(sacc[2 * ksp][0] - m0);
            float p01 = __expf(sacc[2 * ksp][1] - m0);
            float p10 = __expf(sacc[2 * ksp][2] - m1);
            float p11 = __expf(sacc[2 * ksp][3] - m1);
            float p20 = __expf(sacc[2 * ksp + 1][0] - m0);
            float p21 = __expf(sacc[2 * ksp + 1][1] - m0);
            float p30 = __expf(sacc[2 * ksp + 1][2] - m1);
            float p31 = __expf(sacc[2 * ksp + 1][3] - m1);
            l0 += p00 + p01 + p20 + p21;
            l1 += p10 + p11 + p30 + p31;
            split2(p00, p01, ph[ksp][0], pl[ksp][0]);
            split2(p10, p11, ph[ksp][1], pl[ksp][1]);
            split2(p20, p21, ph[ksp][2], pl[ksp][2]);
            split2(p30, p31, ph[ksp][3], pl[ksp][3]);
        }

        // ---- O += P @ V, pass-reordered: ksp outer, nt-groups of 4 ----
#pragma unroll
        for (int ksp = 0; ksp < 4; ksp++) {
            int kc = ksp * 16 + tg * 2;
#pragma unroll
            for (int ng = 0; ng < 2; ng++) {
                unsigned vbh[4][2], vbl[4][2];
#pragma unroll
                for (int j = 0; j < 4; j++) {
                    int n = (ng * 4 + j) * 8 + g;
                    vbh[j][0] = *(const unsigned*)&Vth[n][kc];
                    vbh[j][1] = *(const unsigned*)&Vth[n][kc + 8];
                    vbl[j][0] = *(const unsigned*)&Vtl[n][kc];
                    vbl[j][1] = *(const unsigned*)&Vtl[n][kc + 8];
                }
#pragma unroll
                for (int j = 0; j < 4; j++) {
                    float (&o4)[4] = out[ng * 4 + j];
                    mma16816(o4[0], o4[1], o4[2], o4[3],
                             ph[ksp][0], ph[ksp][1], ph[ksp][2], ph[ksp][3],
                             vbh[j][0], vbh[j][1]);
                }
#pragma unroll
                for (int j = 0; j < 4; j++) {
                    float (&o4)[4] = out[ng * 4 + j];
                    mma16816(o4[0], o4[1], o4[2], o4[3],
                             ph[ksp][0], ph[ksp][1], ph[ksp][2], ph[ksp][3],
                             vbl[j][0], vbl[j][1]);
                }
#pragma unroll
                for (int j = 0; j < 4; j++) {
                    float (&o4)[4] = out[ng * 4 + j];
                    mma16816(o4[0], o4[1], o4[2], o4[3],
                             pl[ksp][0], pl[ksp][1], pl[ksp][2], pl[ksp][3],
                             vbh[j][0], vbh[j][1]);
                }
            }
        }
    }

    l0 += __shfl_xor_sync(0xffffffffu, l0, 1);
    l0 += __shfl_xor_sync(0xffffffffu, l0, 2);
    l1 += __shfl_xor_sync(0xffffffffu, l1, 1);
    l1 += __shfl_xor_sync(0xffffffffu, l1, 2);
    const float inv0 = 1.f / l0;
    const float inv1 = 1.f / l1;

    float* O0 = g_C + (size_t)(b * SS + qrow0 + g) * DD + hoff;
    float* O1 = g_C + (size_t)(b * SS + qrow0 + g + 8) * DD + hoff;
#pragma unroll
    for (int nt = 0; nt < 8; nt++) {
        int d = nt * 8 + tg * 2;
        *(float2*)&O0[d] = make_float2(out[nt][0] * inv0, out[nt][1] * inv0);
        *(float2*)&O1[d] = make_float2(out[nt][2] * inv1, out[nt][3] * inv1);
    }
}

// ----------------------------------------------------------------------------
// Launch
// ----------------------------------------------------------------------------
extern "C" void kernel_launch(void* const* d_in, const int* in_sizes, int n_in,
                              void* d_out, int out_size)
{
    const float* v = (const float*)d_in[0];
    const float* k = (const float*)d_in[1];
    const float* q = (const float*)d_in[2];
    const unsigned char* mask   = (const unsigned char*)d_in[3];
    const unsigned char* semask = (const unsigned char*)d_in[4];
    const float* Wv = (const float*)d_in[5];
    const float* bv = (const float*)d_in[6];
    const float* Wk = (const float*)d_in[7];
    const float* bk = (const float*)d_in[8];
    const float* Wq = (const float*)d_in[9];
    const float* bq = (const float*)d_in[10];
    const float* Wm = (const float*)d_in[11];
    const float* bm = (const float*)d_in[12];

    static float* Qp = nullptr;
    static float* Kp = nullptr;
    static float* Vp = nullptr;
    static float* Cp = nullptr;
    if (!Qp) {
        cudaGetSymbolAddress((void**)&Qp, g_Q);
        cudaGetSymbolAddress((void**)&Kp, g_K);
        cudaGetSymbolAddress((void**)&Vp, g_V);
        cudaGetSymbolAddress((void**)&Cp, g_C);
        cudaFuncSetAttribute(gemm_mma_kernel,
                             cudaFuncAttributeMaxDynamicSharedMemorySize, GSMEM);
    }

    mask_prep_kernel<<<1, 1024>>>(mask, semask);

    dim3 ggrid(DD / 128, MSZ / 128);  // (8, 32)
    gemm_mma_kernel<<<ggrid, 256, GSMEM>>>(v, Wv, bv, Vp, MSZ, DD, DD);
    gemm_mma_kernel<<<ggrid, 256, GSMEM>>>(k, Wk, bk, Kp, MSZ, DD, DD);
    gemm_mma_kernel<<<ggrid, 256, GSMEM>>>(q, Wq, bq, Qp, MSZ, DD, DD);

    dim3 agrid(SS / 128, HH, BB);     // (8, 16, 4)
    attn_mma_kernel<<<agrid, 256>>>();

    gemm_mma_kernel<<<ggrid, 256, GSMEM>>>(Cp, Wm, bm, (float*)d_out, MSZ, DD, DD);
}

// round 14
// speedup vs baseline: 1.3790x; 1.3790x over previous
#include <cuda_runtime.h>
#include <cuda_fp16.h>
#include <math.h>

// Problem constants
#define BB 4
#define SS 1024
#define DD 1024
#define HH 16
#define DHH 64
#define MSZ (BB * SS)  // 4096 rows

// Scratch (no cudaMalloc allowed)
__device__ float g_Q[(size_t)MSZ * DD];
__device__ float g_K[(size_t)MSZ * DD];
__device__ float g_V[(size_t)MSZ * DD];
__device__ float g_C[(size_t)MSZ * DD];
__device__ unsigned char g_mask[BB * SS];

// ----------------------------------------------------------------------------
// Mask canonicalization (verified R4)
// ----------------------------------------------------------------------------
__global__ __launch_bounds__(1024) void mask_prep_kernel(
    const unsigned char* __restrict__ m0,
    const unsigned char* __restrict__ m1)
{
    __shared__ int s_flags;
    const int t = threadIdx.x;
    if (t == 0) s_flags = 0;
    __syncthreads();

    int f1 = 0, f23 = 0;
    for (int i = t; i < BB * SS; i += 1024) {
        unsigned char a = (unsigned char)(m0[i] | m1[i]);
        int r = i & 3;
        if (a) {
            if (r == 1) f1 = 1;
            else if (r >= 2) f23 = 1;
        }
    }
    if (f1)  atomicOr(&s_flags, 1);
    if (f23) atomicOr(&s_flags, 2);
    __syncthreads();

    const int fl = s_flags;
    int code;
    if (fl & 1)      code = 0;  // uint8
    else if (fl & 2) code = 1;  // float32
    else             code = 2;  // int32

    for (int i = t; i < BB * SS; i += 1024) {
        unsigned char mm;
        if (code == 0) {
            mm = (unsigned char)((m0[i] != 0) | (m1[i] != 0));
        } else if (code == 1) {
            mm = (unsigned char)((((const float*)m0)[i] != 0.f) |
                                 (((const float*)m1)[i] != 0.f));
        } else {
            mm = (unsigned char)((((const int*)m0)[i] != 0) |
                                 (((const int*)m1)[i] != 0));
        }
        g_mask[i] = mm;
    }
}

// ----------------------------------------------------------------------------
// Shared helpers (fp16 variants)
// ----------------------------------------------------------------------------
__device__ __forceinline__ void mma16816(
    float& c0, float& c1, float& c2, float& c3,
    unsigned a0, unsigned a1, unsigned a2, unsigned a3,
    unsigned b0, unsigned b1)
{
    asm volatile(
        "mma.sync.aligned.m16n8k16.row.col.f32.f16.f16.f32 "
        "{%0,%1,%2,%3}, {%4,%5,%6,%7}, {%8,%9}, {%0,%1,%2,%3};\n"
        : "+f"(c0), "+f"(c1), "+f"(c2), "+f"(c3)
        : "r"(a0), "r"(a1), "r"(a2), "r"(a3), "r"(b0), "r"(b1));
}

__device__ __forceinline__ void ldsm4(unsigned addr, unsigned& r0, unsigned& r1,
                                      unsigned& r2, unsigned& r3)
{
    asm volatile(
        "ldmatrix.sync.aligned.m8n8.x4.shared.b16 {%0,%1,%2,%3}, [%4];"
        : "=r"(r0), "=r"(r1), "=r"(r2), "=r"(r3) : "r"(addr));
}

// Split two fp32 into packed fp16x2 hi and lo regs.
__device__ __forceinline__ void split2(float x, float y, unsigned& h, unsigned& l)
{
    __half hx = __float2half(x);
    __half hy = __float2half(y);
    __half lx = __float2half(x - __half2float(hx));
    __half ly = __float2half(y - __half2float(hy));
    __half2 hh; hh.x = hx; hh.y = hy;
    __half2 ll; ll.x = lx; ll.y = ly;
    h = *(unsigned*)&hh;
    l = *(unsigned*)&ll;
}

__device__ __forceinline__ void split1(float x, __half& h, __half& l)
{
    h = __float2half(x);
    l = __float2half(x - __half2float(h));
}

// ----------------------------------------------------------------------------
// Tensor-core GEMM (fp16 2-pass): C = A @ W^T + bias.
// Planes: Ah, Al, Wh (no Wl). MMA: Ah.Wh + Al.Wh per k16.
// Double-buffered smem, ldmatrix fragments (R9 structure).
// ----------------------------------------------------------------------------
#define SM_STRIDE 40
#define GPLANE    (128 * SM_STRIDE)
#define PLB       (GPLANE * 2)      // 10240 B per plane
#define STAGEB    (3 * PLB)         // Ah, Al, Wh = 30720 B
#define GSMEM     (2 * STAGEB)      // 61440 B

__global__ __launch_bounds__(256, 2) void gemm_mma_kernel(
    const float* __restrict__ A, const float* __restrict__ W,
    const float* __restrict__ bias, float* __restrict__ C,
    int M, int N, int K)
{
    extern __shared__ __half smdyn[];

    const int tid  = threadIdx.x;
    const int bm   = blockIdx.y * 128;
    const int bn   = blockIdx.x * 128;
    const int wid  = tid >> 5;
    const int lane = tid & 31;
    const int wm   = wid & 1;
    const int wn   = wid >> 1;
    const int g    = lane >> 2;
    const int tg   = lane & 3;

    const int lm = lane >> 3;
    const int lt = lane & 7;
    unsigned smem_u32;
    {
        unsigned long long p = __cvta_generic_to_shared(smdyn);
        smem_u32 = (unsigned)p;
    }
    const unsigned aoff = ((wm * 64 + ((lm & 1) << 3) + lt) * SM_STRIDE +
                           ((lm >> 1) << 3)) * 2;
    const unsigned boff = ((wn * 32 + ((lm >> 1) << 3) + lt) * SM_STRIDE +
                           ((lm & 1) << 3)) * 2;

    float acc[4][4][4];
#pragma unroll
    for (int mt = 0; mt < 4; mt++)
#pragma unroll
        for (int nt = 0; nt < 4; nt++)
#pragma unroll
            for (int e = 0; e < 4; e++) acc[mt][nt][e] = 0.f;

    const int srow = tid >> 3;
    const int sc4  = (tid & 7) << 2;

    float4 av[4], wv[4];
#pragma unroll
    for (int i = 0; i < 4; i++) {
        int row = srow + i * 32;
        av[i] = *(const float4*)&A[(size_t)(bm + row) * K + sc4];
        wv[i] = *(const float4*)&W[(size_t)(bn + row) * K + sc4];
    }
    {
        __half* Ahp = smdyn;
        __half* Alp = smdyn + GPLANE;
        __half* Whp = smdyn + 2 * GPLANE;
#pragma unroll
        for (int i = 0; i < 4; i++) {
            int row = srow + i * 32;
            float ax[4] = {av[i].x, av[i].y, av[i].z, av[i].w};
            float wx[4] = {wv[i].x, wv[i].y, wv[i].z, wv[i].w};
#pragma unroll
            for (int e = 0; e < 4; e++) {
                __half h, l;
                split1(ax[e], h, l);
                Ahp[row * SM_STRIDE + sc4 + e] = h;
                Alp[row * SM_STRIDE + sc4 + e] = l;
                Whp[row * SM_STRIDE + sc4 + e] = __float2half(wx[e]);
            }
        }
    }
    __syncthreads();

    const int NT = K / 32;
    for (int kt = 0; kt < NT; kt++) {
        const int cur = kt & 1;
        if (kt + 1 < NT) {
            int k0 = (kt + 1) * 32;
#pragma unroll
            for (int i = 0; i < 4; i++) {
                int row = srow + i * 32;
                av[i] = *(const float4*)&A[(size_t)(bm + row) * K + k0 + sc4];
                wv[i] = *(const float4*)&W[(size_t)(bn + row) * K + k0 + sc4];
            }
        }

        const unsigned sbase = smem_u32 + (unsigned)cur * STAGEB;
#pragma unroll
        for (int ks = 0; ks < 32; ks += 16) {
            unsigned bh[4][2];
#pragma unroll
            for (int p = 0; p < 2; p++) {
                unsigned ad = sbase + 2 * PLB + boff +
                              (unsigned)(p * 16 * SM_STRIDE + ks) * 2;
                unsigned r0, r1, r2, r3;
                ldsm4(ad, r0, r1, r2, r3);
                bh[2 * p][0] = r0; bh[2 * p][1] = r1;
                bh[2 * p + 1][0] = r2; bh[2 * p + 1][1] = r3;
            }
#pragma unroll
            for (int mt = 0; mt < 4; mt++) {
                unsigned ad = sbase + aoff +
                              (unsigned)(mt * 16 * SM_STRIDE + ks) * 2;
                unsigned ah0, ah1, ah2, ah3, al0, al1, al2, al3;
                ldsm4(ad, ah0, ah1, ah2, ah3);
                ldsm4(ad + PLB, al0, al1, al2, al3);
#pragma unroll
                for (int nt = 0; nt < 4; nt++) {
                    mma16816(acc[mt][nt][0], acc[mt][nt][1],
                             acc[mt][nt][2], acc[mt][nt][3],
                             ah0, ah1, ah2, ah3, bh[nt][0], bh[nt][1]);
                }
#pragma unroll
                for (int nt = 0; nt < 4; nt++) {
                    mma16816(acc[mt][nt][0], acc[mt][nt][1],
                             acc[mt][nt][2], acc[mt][nt][3],
                             al0, al1, al2, al3, bh[nt][0], bh[nt][1]);
                }
            }
        }

        if (kt + 1 < NT) {
            int nxt = cur ^ 1;
            __syncthreads();
            __half* Ahp = smdyn + nxt * 3 * GPLANE;
            __half* Alp = Ahp + GPLANE;
            __half* Whp = Ahp + 2 * GPLANE;
#pragma unroll
            for (int i = 0; i < 4; i++) {
                int row = srow + i * 32;
                float ax[4] = {av[i].x, av[i].y, av[i].z, av[i].w};
                float wx[4] = {wv[i].x, wv[i].y, wv[i].z, wv[i].w};
#pragma unroll
                for (int e = 0; e < 4; e++) {
                    __half h, l;
                    split1(ax[e], h, l);
                    Ahp[row * SM_STRIDE + sc4 + e] = h;
                    Alp[row * SM_STRIDE + sc4 + e] = l;
                    Whp[row * SM_STRIDE + sc4 + e] = __float2half(wx[e]);
                }
            }
            __syncthreads();
        }
    }

    // Epilogue
#pragma unroll
    for (int nt = 0; nt < 4; nt++) {
        int col = bn + wn * 32 + nt * 8 + tg * 2;
        float b0 = bias[col];
        float b1 = bias[col + 1];
#pragma unroll
        for (int mt = 0; mt < 4; mt++) {
            int row = bm + wm * 64 + mt * 16 + g;
            float* p0 = C + (size_t)row * N + col;
            float* p1 = C + (size_t)(row + 8) * N + col;
            p0[0] = acc[mt][nt][0] + b0;
            p0[1] = acc[mt][nt][1] + b1;
            p1[0] = acc[mt][nt][2] + b0;
            p1[1] = acc[mt][nt][3] + b1;
        }
    }
}

// ----------------------------------------------------------------------------
// Tensor-core flash attention (R8 structure, fp16 2-pass).
// K and V stored hi-only in smem; Q and P carry hi+lo in registers.
// S = (Qh+Ql).Kh ; O += (Ph+Pl).Vh
// ----------------------------------------------------------------------------
#define AST 72

__global__ __launch_bounds__(256) void attn_mma_kernel()
{
    const int tid  = threadIdx.x;
    const int wid  = tid >> 5;
    const int lane = tid & 31;
    const int g    = lane >> 2;
    const int tg   = lane & 3;
    const int qb   = blockIdx.x * 128;
    const int h    = blockIdx.y;
    const int b    = blockIdx.z;
    const int hoff = h * DHH;
    const int qrow0 = qb + wid * 16;

    __shared__ __align__(16) __half Kh[64][AST];
    __shared__ __align__(16) __half Vth[64][AST];  // [dim][key]
    __shared__ unsigned char smask[64];

    unsigned qh[4][4], ql[4][4];
    {
        const float* Q0 = g_Q + (size_t)(b * SS + qrow0 + g) * DD + hoff;
        const float* Q1 = g_Q + (size_t)(b * SS + qrow0 + g + 8) * DD + hoff;
#pragma unroll
        for (int ks = 0; ks < 4; ks++) {
            int d0 = ks * 16 + tg * 2;
            float2 f0 = *(const float2*)&Q0[d0];
            float2 f1 = *(const float2*)&Q1[d0];
            float2 f2 = *(const float2*)&Q0[d0 + 8];
            float2 f3 = *(const float2*)&Q1[d0 + 8];
            split2(f0.x, f0.y, qh[ks][0], ql[ks][0]);
            split2(f1.x, f1.y, qh[ks][1], ql[ks][1]);
            split2(f2.x, f2.y, qh[ks][2], ql[ks][2]);
            split2(f3.x, f3.y, qh[ks][3], ql[ks][3]);
        }
    }

    float out[8][4];
#pragma unroll
    for (int nt = 0; nt < 8; nt++)
#pragma unroll
        for (int e = 0; e < 4; e++) out[nt][e] = 0.f;
    float m0 = -INFINITY, m1 = -INFINITY;
    float l0 = 0.f, l1 = 0.f;

    const int krow = tid >> 2;
    const int kc4  = (tid & 3) * 16;

    for (int kt = 0; kt < SS / 64; kt++) {
        float4 kv[4], vv[4];
        const float* Kg = g_K + (size_t)(b * SS + kt * 64 + krow) * DD + hoff + kc4;
        const float* Vg = g_V + (size_t)(b * SS + kt * 64 + krow) * DD + hoff + kc4;
#pragma unroll
        for (int i = 0; i < 4; i++) {
            kv[i] = *(const float4*)&Kg[i * 4];
            vv[i] = *(const float4*)&Vg[i * 4];
        }
        __syncthreads();
#pragma unroll
        for (int i = 0; i < 4; i++) {
            float kx[4] = {kv[i].x, kv[i].y, kv[i].z, kv[i].w};
            float vx[4] = {vv[i].x, vv[i].y, vv[i].z, vv[i].w};
#pragma unroll
            for (int e = 0; e < 4; e++) {
                int d = kc4 + i * 4 + e;
                Kh[krow][d] = __float2half(kx[e]);
                Vth[d][krow] = __float2half(vx[e]);  // transpose
            }
        }
        if (tid < 64) smask[tid] = g_mask[b * SS + kt * 64 + tid];
        __syncthreads();

        // ---- S = Q @ K^T (2-pass) ----
        float sacc[8][4];
#pragma unroll
        for (int nt = 0; nt < 8; nt++) {
#pragma unroll
            for (int e = 0; e < 4; e++) sacc[nt][e] = 0.f;
            int n = nt * 8 + g;
#pragma unroll
            for (int ks = 0; ks < 4; ks++) {
                int kc = ks * 16 + tg * 2;
                unsigned bh0 = *(const unsigned*)&Kh[n][kc];
                unsigned bh1 = *(const unsigned*)&Kh[n][kc + 8];
                mma16816(sacc[nt][0], sacc[nt][1], sacc[nt][2], sacc[nt][3],
                         qh[ks][0], qh[ks][1], qh[ks][2], qh[ks][3], bh0, bh1);
                mma16816(sacc[nt][0], sacc[nt][1], sacc[nt][2], sacc[nt][3],
                         ql[ks][0], ql[ks][1], ql[ks][2], ql[ks][3], bh0, bh1);
            }
        }

        float tmax0 = -INFINITY, tmax1 = -INFINITY;
#pragma unroll
        for (int nt = 0; nt < 8; nt++) {
            bool msk0 = smask[nt * 8 + tg * 2] != 0;
            bool msk1 = smask[nt * 8 + tg * 2 + 1] != 0;
            sacc[nt][0] = msk0 ? -1e9f : sacc[nt][0] * 0.125f;
            sacc[nt][1] = msk1 ? -1e9f : sacc[nt][1] * 0.125f;
            sacc[nt][2] = msk0 ? -1e9f : sacc[nt][2] * 0.125f;
            sacc[nt][3] = msk1 ? -1e9f : sacc[nt][3] * 0.125f;
            tmax0 = fmaxf(tmax0, fmaxf(sacc[nt][0], sacc[nt][1]));
            tmax1 = fmaxf(tmax1, fmaxf(sacc[nt][2], sacc[nt][3]));
        }
        tmax0 = fmaxf(tmax0, __shfl_xor_sync(0xffffffffu, tmax0, 1));
        tmax0 = fmaxf(tmax0, __shfl_xor_sync(0xffffffffu, tmax0, 2));
        tmax1 = fmaxf(tmax1, __shfl_xor_sync(0xffffffffu, tmax1, 1));
        tmax1 = fmaxf(tmax1, __shfl_xor_sync(0xffffffffu, tmax1, 2));

        float mn0 = fmaxf(m0, tmax0);
        float mn1 = fmaxf(m1, tmax1);
        float corr0 = __expf(m0 - mn0);
        float corr1 = __expf(m1 - mn1);
        m0 = mn0; m1 = mn1;
        l0 *= corr0; l1 *= corr1;
#pragma unroll
        for (int nt = 0; nt < 8; nt++) {
            out[nt][0] *= corr0; out[nt][1] *= corr0;
            out[nt][2] *= corr1; out[nt][3] *= corr1;
        }

        // ---- P = exp(S - m), fp16 hi/lo A-fragments ----
        unsigned ph[4][4], pl[4][4];
#pragma unroll
        for (int ksp = 0; ksp < 4; ksp++) {
            float p00 = __expf(sacc[2 * ksp][0] - m0);
            float p01 = __expf(sacc[2 * ksp][1] - m0);
            float p10 = __expf(sacc[2 * ksp][2] - m1);
            float p11 = __expf(sacc[2 * ksp][3] - m1);
            float p20 = __expf(sacc[2 * ksp + 1][0] - m0);
            float p21 = __expf(sacc[2 * ksp + 1][1] - m0);
            float p30 = __expf(sacc[2 * ksp + 1][2] - m1);
            float p31 = __expf(sacc[2 * ksp + 1][3] - m1);
            l0 += p00 + p01 + p20 + p21;
            l1 += p10 + p11 + p30 + p31;
            split2(p00, p01, ph[ksp][0], pl[ksp][0]);
            split2(p10, p11, ph[ksp][1], pl[ksp][1]);
            split2(p20, p21, ph[ksp][2], pl[ksp][2]);
            split2(p30, p31, ph[ksp][3], pl[ksp][3]);
        }

        // ---- O += P @ V (2-pass) ----
#pragma unroll
        for (int nt = 0; nt < 8; nt++) {
            int n = nt * 8 + g;
#pragma unroll
            for (int ksp = 0; ksp < 4; ksp++) {
                int kc = ksp * 16 + tg * 2;
                unsigned bh0 = *(const unsigned*)&Vth[n][kc];
                unsigned bh1 = *(const unsigned*)&Vth[n][kc + 8];
                mma16816(out[nt][0], out[nt][1], out[nt][2], out[nt][3],
                         ph[ksp][0], ph[ksp][1], ph[ksp][2], ph[ksp][3], bh0, bh1);
                mma16816(out[nt][0], out[nt][1], out[nt][2], out[nt][3],
                         pl[ksp][0], pl[ksp][1], pl[ksp][2], pl[ksp][3], bh0, bh1);
            }
        }
    }

    l0 += __shfl_xor_sync(0xffffffffu, l0, 1);
    l0 += __shfl_xor_sync(0xffffffffu, l0, 2);
    l1 += __shfl_xor_sync(0xffffffffu, l1, 1);
    l1 += __shfl_xor_sync(0xffffffffu, l1, 2);
    const float inv0 = 1.f / l0;
    const float inv1 = 1.f / l1;

    float* O0 = g_C + (size_t)(b * SS + qrow0 + g) * DD + hoff;
    float* O1 = g_C + (size_t)(b * SS + qrow0 + g + 8) * DD + hoff;
#pragma unroll
    for (int nt = 0; nt < 8; nt++) {
        int d = nt * 8 + tg * 2;
        *(float2*)&O0[d] = make_float2(out[nt][0] * inv0, out[nt][1] * inv0);
        *(float2*)&O1[d] = make_float2(out[nt][2] * inv1, out[nt][3] * inv1);
    }
}

// ----------------------------------------------------------------------------
// Launch
// ----------------------------------------------------------------------------
extern "C" void kernel_launch(void* const* d_in, const int* in_sizes, int n_in,
                              void* d_out, int out_size)
{
    const float* v = (const float*)d_in[0];
    const float* k = (const float*)d_in[1];
    const float* q = (const float*)d_in[2];
    const unsigned char* mask   = (const unsigned char*)d_in[3];
    const unsigned char* semask = (const unsigned char*)d_in[4];
    const float* Wv = (const float*)d_in[5];
    const float* bv = (const float*)d_in[6];
    const float* Wk = (const float*)d_in[7];
    const float* bk = (const float*)d_in[8];
    const float* Wq = (const float*)d_in[9];
    const float* bq = (const float*)d_in[10];
    const float* Wm = (const float*)d_in[11];
    const float* bm = (const float*)d_in[12];

    static float* Qp = nullptr;
    static float* Kp = nullptr;
    static float* Vp = nullptr;
    static float* Cp = nullptr;
    if (!Qp) {
        cudaGetSymbolAddress((void**)&Qp, g_Q);
        cudaGetSymbolAddress((void**)&Kp, g_K);
        cudaGetSymbolAddress((void**)&Vp, g_V);
        cudaGetSymbolAddress((void**)&Cp, g_C);
        cudaFuncSetAttribute(gemm_mma_kernel,
                             cudaFuncAttributeMaxDynamicSharedMemorySize, GSMEM);
    }

    mask_prep_kernel<<<1, 1024>>>(mask, semask);

    dim3 ggrid(DD / 128, MSZ / 128);  // (8, 32)
    gemm_mma_kernel<<<ggrid, 256, GSMEM>>>(v, Wv, bv, Vp, MSZ, DD, DD);
    gemm_mma_kernel<<<ggrid, 256, GSMEM>>>(k, Wk, bk, Kp, MSZ, DD, DD);
    gemm_mma_kernel<<<ggrid, 256, GSMEM>>>(q, Wq, bq, Qp, MSZ, DD, DD);

    dim3 agrid(SS / 128, HH, BB);     // (8, 16, 4)
    attn_mma_kernel<<<agrid, 256>>>();

    gemm_mma_kernel<<<ggrid, 256, GSMEM>>>(Cp, Wm, bm, (float*)d_out, MSZ, DD, DD);
}

// round 16
// speedup vs baseline: 1.6523x; 1.1982x over previous
#include <cuda_runtime.h>
#include <cuda_fp16.h>
#include <math.h>

// Problem constants
#define BB 4
#define SS 1024
#define DD 1024
#define HH 16
#define DHH 64
#define MSZ (BB * SS)  // 4096 rows

// Scratch (no cudaMalloc allowed)
__device__ float  g_Q[(size_t)MSZ * DD];
__device__ float  g_C[(size_t)MSZ * DD];
__device__ __half g_K16[(size_t)MSZ * DD];      // K projection, fp16 hi
__device__ __half g_V16h[(size_t)MSZ * DD];     // V projection, fp16 hi, [s][D]
__device__ __half g_V16T[(size_t)MSZ * DD];     // V transposed  [b][h][d][s]
__device__ unsigned char g_mask[BB * SS];

// ----------------------------------------------------------------------------
// Mask canonicalization (verified R4)
// ----------------------------------------------------------------------------
__global__ __launch_bounds__(1024) void mask_prep_kernel(
    const unsigned char* __restrict__ m0,
    const unsigned char* __restrict__ m1)
{
    __shared__ int s_flags;
    const int t = threadIdx.x;
    if (t == 0) s_flags = 0;
    __syncthreads();

    int f1 = 0, f23 = 0;
    for (int i = t; i < BB * SS; i += 1024) {
        unsigned char a = (unsigned char)(m0[i] | m1[i]);
        int r = i & 3;
        if (a) {
            if (r == 1) f1 = 1;
            else if (r >= 2) f23 = 1;
        }
    }
    if (f1)  atomicOr(&s_flags, 1);
    if (f23) atomicOr(&s_flags, 2);
    __syncthreads();

    const int fl = s_flags;
    int code;
    if (fl & 1)      code = 0;  // uint8
    else if (fl & 2) code = 1;  // float32
    else             code = 2;  // int32

    for (int i = t; i < BB * SS; i += 1024) {
        unsigned char mm;
        if (code == 0) {
            mm = (unsigned char)((m0[i] != 0) | (m1[i] != 0));
        } else if (code == 1) {
            mm = (unsigned char)((((const float*)m0)[i] != 0.f) |
                                 (((const float*)m1)[i] != 0.f));
        } else {
            mm = (unsigned char)((((const int*)m0)[i] != 0) |
                                 (((const int*)m1)[i] != 0));
        }
        g_mask[i] = mm;
    }
}

// ----------------------------------------------------------------------------
// Shared helpers (fp16)
// ----------------------------------------------------------------------------
__device__ __forceinline__ void mma16816(
    float& c0, float& c1, float& c2, float& c3,
    unsigned a0, unsigned a1, unsigned a2, unsigned a3,
    unsigned b0, unsigned b1)
{
    asm volatile(
        "mma.sync.aligned.m16n8k16.row.col.f32.f16.f16.f32 "
        "{%0,%1,%2,%3}, {%4,%5,%6,%7}, {%8,%9}, {%0,%1,%2,%3};\n"
        : "+f"(c0), "+f"(c1), "+f"(c2), "+f"(c3)
        : "r"(a0), "r"(a1), "r"(a2), "r"(a3), "r"(b0), "r"(b1));
}

__device__ __forceinline__ void ldsm4(unsigned addr, unsigned& r0, unsigned& r1,
                                      unsigned& r2, unsigned& r3)
{
    asm volatile(
        "ldmatrix.sync.aligned.m8n8.x4.shared.b16 {%0,%1,%2,%3}, [%4];"
        : "=r"(r0), "=r"(r1), "=r"(r2), "=r"(r3) : "r"(addr));
}

__device__ __forceinline__ void cpasync16(unsigned saddr, const void* gaddr)
{
    asm volatile("cp.async.cg.shared.global [%0], [%1], 16;\n"
                 :: "r"(saddr), "l"(gaddr));
}
#define CP_COMMIT() asm volatile("cp.async.commit_group;\n" ::: "memory")
#define CP_WAIT1()  asm volatile("cp.async.wait_group 1;\n" ::: "memory")
#define CP_WAIT0()  asm volatile("cp.async.wait_group 0;\n" ::: "memory")

__device__ __forceinline__ void split2(float x, float y, unsigned& h, unsigned& l)
{
    __half hx = __float2half(x);
    __half hy = __float2half(y);
    __half lx = __float2half(x - __half2float(hx));
    __half ly = __float2half(y - __half2float(hy));
    __half2 hh; hh.x = hx; hh.y = hy;
    __half2 ll; ll.x = lx; ll.y = ly;
    h = *(unsigned*)&hh;
    l = *(unsigned*)&ll;
}

__device__ __forceinline__ void split1(float x, __half& h, __half& l)
{
    h = __float2half(x);
    l = __float2half(x - __half2float(h));
}

// Pack two floats into fp16x2 register bits.
__device__ __forceinline__ unsigned pack_h2(float a, float b)
{
    __half2 h2; h2.x = __float2half(a); h2.y = __float2half(b);
    return *(unsigned*)&h2;
}

__device__ __forceinline__ void store2(float* p, float a, float b)
{
    p[0] = a; p[1] = b;
}
__device__ __forceinline__ void store2(__half* p, float a, float b)
{
    __half2 h2; h2.x = __float2half(a); h2.y = __float2half(b);
    *(__half2*)p = h2;
}

// ----------------------------------------------------------------------------
// Tensor-core GEMM (fp16 2-pass, verified R14): C = A @ W^T + bias.
// Templated output type: float (Q, final) or __half (K, V).
// ----------------------------------------------------------------------------
#define SM_STRIDE 40
#define GPLANE    (128 * SM_STRIDE)
#define PLB       (GPLANE * 2)
#define STAGEB    (3 * PLB)
#define GSMEM     (2 * STAGEB)

template <typename OutT>
__global__ __launch_bounds__(256, 2) void gemm_mma_kernel(
    const float* __restrict__ A, const float* __restrict__ W,
    const float* __restrict__ bias, OutT* __restrict__ C,
    int M, int N, int K)
{
    extern __shared__ __half smdyn[];

    const int tid  = threadIdx.x;
    const int bm   = blockIdx.y * 128;
    const int bn   = blockIdx.x * 128;
    const int wid  = tid >> 5;
    const int lane = tid & 31;
    const int wm   = wid & 1;
    const int wn   = wid >> 1;
    const int g    = lane >> 2;
    const int tg   = lane & 3;

    const int lm = lane >> 3;
    const int lt = lane & 7;
    unsigned smem_u32;
    {
        unsigned long long p = __cvta_generic_to_shared(smdyn);
        smem_u32 = (unsigned)p;
    }
    const unsigned aoff = ((wm * 64 + ((lm & 1) << 3) + lt) * SM_STRIDE +
                           ((lm >> 1) << 3)) * 2;
    const unsigned boff = ((wn * 32 + ((lm >> 1) << 3) + lt) * SM_STRIDE +
                           ((lm & 1) << 3)) * 2;

    float acc[4][4][4];
#pragma unroll
    for (int mt = 0; mt < 4; mt++)
#pragma unroll
        for (int nt = 0; nt < 4; nt++)
#pragma unroll
            for (int e = 0; e < 4; e++) acc[mt][nt][e] = 0.f;

    const int srow = tid >> 3;
    const int sc4  = (tid & 7) << 2;

    float4 av[4], wv[4];
#pragma unroll
    for (int i = 0; i < 4; i++) {
        int row = srow + i * 32;
        av[i] = *(const float4*)&A[(size_t)(bm + row) * K + sc4];
        wv[i] = *(const float4*)&W[(size_t)(bn + row) * K + sc4];
    }
    {
        __half* Ahp = smdyn;
        __half* Alp = smdyn + GPLANE;
        __half* Whp = smdyn + 2 * GPLANE;
#pragma unroll
        for (int i = 0; i < 4; i++) {
            int row = srow + i * 32;
            float ax[4] = {av[i].x, av[i].y, av[i].z, av[i].w};
            float wx[4] = {wv[i].x, wv[i].y, wv[i].z, wv[i].w};
#pragma unroll
            for (int e = 0; e < 4; e++) {
                __half h, l;
                split1(ax[e], h, l);
                Ahp[row * SM_STRIDE + sc4 + e] = h;
                Alp[row * SM_STRIDE + sc4 + e] = l;
                Whp[row * SM_STRIDE + sc4 + e] = __float2half(wx[e]);
            }
        }
    }
    __syncthreads();

    const int NT = K / 32;
    for (int kt = 0; kt < NT; kt++) {
        const int cur = kt & 1;
        if (kt + 1 < NT) {
            int k0 = (kt + 1) * 32;
#pragma unroll
            for (int i = 0; i < 4; i++) {
                int row = srow + i * 32;
                av[i] = *(const float4*)&A[(size_t)(bm + row) * K + k0 + sc4];
                wv[i] = *(const float4*)&W[(size_t)(bn + row) * K + k0 + sc4];
            }
        }

        const unsigned sbase = smem_u32 + (unsigned)cur * STAGEB;
#pragma unroll
        for (int ks = 0; ks < 32; ks += 16) {
            unsigned bh[4][2];
#pragma unroll
            for (int p = 0; p < 2; p++) {
                unsigned ad = sbase + 2 * PLB + boff +
                              (unsigned)(p * 16 * SM_STRIDE + ks) * 2;
                unsigned r0, r1, r2, r3;
                ldsm4(ad, r0, r1, r2, r3);
                bh[2 * p][0] = r0; bh[2 * p][1] = r1;
                bh[2 * p + 1][0] = r2; bh[2 * p + 1][1] = r3;
            }
#pragma unroll
            for (int mt = 0; mt < 4; mt++) {
                unsigned ad = sbase + aoff +
                              (unsigned)(mt * 16 * SM_STRIDE + ks) * 2;
                unsigned ah0, ah1, ah2, ah3, al0, al1, al2, al3;
                ldsm4(ad, ah0, ah1, ah2, ah3);
                ldsm4(ad + PLB, al0, al1, al2, al3);
#pragma unroll
                for (int nt = 0; nt < 4; nt++) {
                    mma16816(acc[mt][nt][0], acc[mt][nt][1],
                             acc[mt][nt][2], acc[mt][nt][3],
                             ah0, ah1, ah2, ah3, bh[nt][0], bh[nt][1]);
                }
#pragma unroll
                for (int nt = 0; nt < 4; nt++) {
                    mma16816(acc[mt][nt][0], acc[mt][nt][1],
                             acc[mt][nt][2], acc[mt][nt][3],
                             al0, al1, al2, al3, bh[nt][0], bh[nt][1]);
                }
            }
        }

        if (kt + 1 < NT) {
            int nxt = cur ^ 1;
            __syncthreads();
            __half* Ahp = smdyn + nxt * 3 * GPLANE;
            __half* Alp = Ahp + GPLANE;
            __half* Whp = Ahp + 2 * GPLANE;
#pragma unroll
            for (int i = 0; i < 4; i++) {
                int row = srow + i * 32;
                float ax[4] = {av[i].x, av[i].y, av[i].z, av[i].w};
                float wx[4] = {wv[i].x, wv[i].y, wv[i].z, wv[i].w};
#pragma unroll
                for (int e = 0; e < 4; e++) {
                    __half h, l;
                    split1(ax[e], h, l);
                    Ahp[row * SM_STRIDE + sc4 + e] = h;
                    Alp[row * SM_STRIDE + sc4 + e] = l;
                    Whp[row * SM_STRIDE + sc4 + e] = __float2half(wx[e]);
                }
            }
            __syncthreads();
        }
    }

    // Epilogue
#pragma unroll
    for (int nt = 0; nt < 4; nt++) {
        int col = bn + wn * 32 + nt * 8 + tg * 2;
        float b0 = bias[col];
        float b1 = bias[col + 1];
#pragma unroll
        for (int mt = 0; mt < 4; mt++) {
            int row = bm + wm * 64 + mt * 16 + g;
            store2(C + (size_t)row * N + col, acc[mt][nt][0] + b0, acc[mt][nt][1] + b1);
            store2(C + (size_t)(row + 8) * N + col, acc[mt][nt][2] + b0, acc[mt][nt][3] + b1);
        }
    }
}

// ----------------------------------------------------------------------------
// V transpose: g_V16h [b*SS+s][D] -> g_V16T [b][h][d][s]  (fp16 -> fp16)
// Block: one (b, h, 64-s tile). 256 threads.
// ----------------------------------------------------------------------------
__global__ __launch_bounds__(256) void vtrans_kernel()
{
    __shared__ __half vt[64][72];
    const int tid = threadIdx.x;
    const int s0  = blockIdx.x * 64;
    const int h   = blockIdx.y;
    const int b   = blockIdx.z;

#pragma unroll
    for (int i = 0; i < 2; i++) {
        int c = tid + i * 256;           // 0..511
        int srow = c >> 3, c8 = c & 7;
        uint4 val = *(const uint4*)&g_V16h[(size_t)(b * SS + s0 + srow) * DD +
                                           h * DHH + c8 * 8];
        __half tmp[8];
        *(uint4*)tmp = val;
#pragma unroll
        for (int e = 0; e < 8; e++) vt[c8 * 8 + e][srow] = tmp[e];
    }
    __syncthreads();
#pragma unroll
    for (int i = 0; i < 2; i++) {
        int c = tid + i * 256;
        int drow = c >> 3, c8 = c & 7;
        uint4 val = *(const uint4*)&vt[drow][c8 * 8];
        *(uint4*)&g_V16T[((size_t)(b * HH + h) * DHH + drow) * SS + s0 + c8 * 8] = val;
    }
}

// ----------------------------------------------------------------------------
// Flash attention: fp16, QK 2-pass, PV 1-pass.
// K/V tiles staged by cp.async from pre-converted fp16 (double-buffered).
// ----------------------------------------------------------------------------
#define AST 72
#define APLB (64 * AST * 2)  // 9216 B per plane

__global__ __launch_bounds__(256) void attn_mma_kernel()
{
    const int tid  = threadIdx.x;
    const int wid  = tid >> 5;
    const int lane = tid & 31;
    const int g    = lane >> 2;
    const int tg   = lane & 3;
    const int qb   = blockIdx.x * 128;
    const int h    = blockIdx.y;
    const int b    = blockIdx.z;
    const int hoff = h * DHH;
    const int qrow0 = qb + wid * 16;

    __shared__ __align__(16) __half Kh[2][64][AST];
    __shared__ __align__(16) __half Vt[2][64][AST];  // [dim][key]
    __shared__ unsigned char smask[64];

    unsigned kh_u32, vt_u32;
    {
        unsigned long long p = __cvta_generic_to_shared(&Kh[0][0][0]);
        kh_u32 = (unsigned)p;
        p = __cvta_generic_to_shared(&Vt[0][0][0]);
        vt_u32 = (unsigned)p;
    }

    // Q fragments (fp32 -> hi/lo fp16)
    unsigned qh[4][4], ql[4][4];
    {
        const float* Q0 = g_Q + (size_t)(b * SS + qrow0 + g) * DD + hoff;
        const float* Q1 = g_Q + (size_t)(b * SS + qrow0 + g + 8) * DD + hoff;
#pragma unroll
        for (int ks = 0; ks < 4; ks++) {
            int d0 = ks * 16 + tg * 2;
            float2 f0 = *(const float2*)&Q0[d0];
            float2 f1 = *(const float2*)&Q1[d0];
            float2 f2 = *(const float2*)&Q0[d0 + 8];
            float2 f3 = *(const float2*)&Q1[d0 + 8];
            split2(f0.x, f0.y, qh[ks][0], ql[ks][0]);
            split2(f1.x, f1.y, qh[ks][1], ql[ks][1]);
            split2(f2.x, f2.y, qh[ks][2], ql[ks][2]);
            split2(f3.x, f3.y, qh[ks][3], ql[ks][3]);
        }
    }

    // Staging: 2 K-chunks + 2 V-chunks (16 B each) per thread per tile.
    const int c0r = tid >> 3;         // row for chunk c=tid
    const int c0c = (tid & 7) * 8;    // half-offset
    const int c1r = (tid + 256) >> 3;
    const int c1c = ((tid + 256) & 7) * 8;

    auto stage = [&](int s, int kt) {
        unsigned kb = kh_u32 + (unsigned)s * APLB;
        unsigned vb = vt_u32 + (unsigned)s * APLB;
        const __half* Ksrc = g_K16 + (size_t)(b * SS + kt * 64) * DD + hoff;
        const __half* Vsrc = g_V16T + ((size_t)(b * HH + h) * DHH) * SS + kt * 64;
        cpasync16(kb + (unsigned)(c0r * AST + c0c) * 2, Ksrc + (size_t)c0r * DD + c0c);
        cpasync16(kb + (unsigned)(c1r * AST + c1c) * 2, Ksrc + (size_t)c1r * DD + c1c);
        cpasync16(vb + (unsigned)(c0r * AST + c0c) * 2, Vsrc + (size_t)c0r * SS + c0c);
        cpasync16(vb + (unsigned)(c1r * AST + c1c) * 2, Vsrc + (size_t)c1r * SS + c1c);
    };

    float out[8][4];
#pragma unroll
    for (int nt = 0; nt < 8; nt++)
#pragma unroll
        for (int e = 0; e < 4; e++) out[nt][e] = 0.f;
    float m0 = -INFINITY, m1 = -INFINITY;
    float l0 = 0.f, l1 = 0.f;

    stage(0, 0);
    CP_COMMIT();

    const int NTK = SS / 64;  // 16
    for (int kt = 0; kt < NTK; kt++) {
        const int cur = kt & 1;
        __syncthreads();  // reads of buffer (kt+1)&1 (from tile kt-1) complete
        if (kt + 1 < NTK) {
            stage(cur ^ 1, kt + 1);
            CP_COMMIT();
            CP_WAIT1();
        } else {
            CP_WAIT0();
        }
        if (tid < 64) smask[tid] = g_mask[b * SS + kt * 64 + tid];
        __syncthreads();  // tile kt data + mask visible

        // ---- S = Q @ K^T (2-pass) ----
        float sacc[8][4];
#pragma unroll
        for (int nt = 0; nt < 8; nt++) {
#pragma unroll
            for (int e = 0; e < 4; e++) sacc[nt][e] = 0.f;
            int n = nt * 8 + g;
#pragma unroll
            for (int ks = 0; ks < 4; ks++) {
                int kc = ks * 16 + tg * 2;
                unsigned bh0 = *(const unsigned*)&Kh[cur][n][kc];
                unsigned bh1 = *(const unsigned*)&Kh[cur][n][kc + 8];
                mma16816(sacc[nt][0], sacc[nt][1], sacc[nt][2], sacc[nt][3],
                         qh[ks][0], qh[ks][1], qh[ks][2], qh[ks][3], bh0, bh1);
                mma16816(sacc[nt][0], sacc[nt][1], sacc[nt][2], sacc[nt][3],
                         ql[ks][0], ql[ks][1], ql[ks][2], ql[ks][3], bh0, bh1);
            }
        }

        float tmax0 = -INFINITY, tmax1 = -INFINITY;
#pragma unroll
        for (int nt = 0; nt < 8; nt++) {
            bool msk0 = smask[nt * 8 + tg * 2] != 0;
            bool msk1 = smask[nt * 8 + tg * 2 + 1] != 0;
            sacc[nt][0] = msk0 ? -1e9f : sacc[nt][0] * 0.125f;
            sacc[nt][1] = msk1 ? -1e9f : sacc[nt][1] * 0.125f;
            sacc[nt][2] = msk0 ? -1e9f : sacc[nt][2] * 0.125f;
            sacc[nt][3] = msk1 ? -1e9f : sacc[nt][3] * 0.125f;
            tmax0 = fmaxf(tmax0, fmaxf(sacc[nt][0], sacc[nt][1]));
            tmax1 = fmaxf(tmax1, fmaxf(sacc[nt][2], sacc[nt][3]));
        }
        tmax0 = fmaxf(tmax0, __shfl_xor_sync(0xffffffffu, tmax0, 1));
        tmax0 = fmaxf(tmax0, __shfl_xor_sync(0xffffffffu, tmax0, 2));
        tmax1 = fmaxf(tmax1, __shfl_xor_sync(0xffffffffu, tmax1, 1));
        tmax1 = fmaxf(tmax1, __shfl_xor_sync(0xffffffffu, tmax1, 2));

        float mn0 = fmaxf(m0, tmax0);
        float mn1 = fmaxf(m1, tmax1);
        float corr0 = __expf(m0 - mn0);
        float corr1 = __expf(m1 - mn1);
        m0 = mn0; m1 = mn1;
        l0 *= corr0; l1 *= corr1;
#pragma unroll
        for (int nt = 0; nt < 8; nt++) {
            out[nt][0] *= corr0; out[nt][1] *= corr0;
            out[nt][2] *= corr1; out[nt][3] *= corr1;
        }

        // ---- P = exp(S - m), fp16 hi-only A-fragments ----
        unsigned ph[4][4];
#pragma unroll
        for (int ksp = 0; ksp < 4; ksp++) {
            float p00 = __expf(sacc[2 * ksp][0] - m0);
            float p01 = __expf(sacc[2 * ksp][1] - m0);
            float p10 = __expf(sacc[2 * ksp][2] - m1);
            float p11 = __expf(sacc[2 * ksp][3] - m1);
            float p20 = __expf(sacc[2 * ksp + 1][0] - m0);
            float p21 = __expf(sacc[2 * ksp + 1][1] - m0);
            float p30 = __expf(sacc[2 * ksp + 1][2] - m1);
            float p31 = __expf(sacc[2 * ksp + 1][3] - m1);
            l0 += p00 + p01 + p20 + p21;
            l1 += p10 + p11 + p30 + p31;
            ph[ksp][0] = pack_h2(p00, p01);
            ph[ksp][1] = pack_h2(p10, p11);
            ph[ksp][2] = pack_h2(p20, p21);
            ph[ksp][3] = pack_h2(p30, p31);
        }

        // ---- O += P @ V (1-pass) ----
#pragma unroll
        for (int nt = 0; nt < 8; nt++) {
            int n = nt * 8 + g;
#pragma unroll
            for (int ksp = 0; ksp < 4; ksp++) {
                int kc = ksp * 16 + tg * 2;
                unsigned bh0 = *(const unsigned*)&Vt[cur][n][kc];
                unsigned bh1 = *(const unsigned*)&Vt[cur][n][kc + 8];
                mma16816(out[nt][0], out[nt][1], out[nt][2], out[nt][3],
                         ph[ksp][0], ph[ksp][1], ph[ksp][2], ph[ksp][3], bh0, bh1);
            }
        }
    }

    l0 += __shfl_xor_sync(0xffffffffu, l0, 1);
    l0 += __shfl_xor_sync(0xffffffffu, l0, 2);
    l1 += __shfl_xor_sync(0xffffffffu, l1, 1);
    l1 += __shfl_xor_sync(0xffffffffu, l1, 2);
    const float inv0 = 1.f / l0;
    const float inv1 = 1.f / l1;

    float* O0 = g_C + (size_t)(b * SS + qrow0 + g) * DD + hoff;
    float* O1 = g_C + (size_t)(b * SS + qrow0 + g + 8) * DD + hoff;
#pragma unroll
    for (int nt = 0; nt < 8; nt++) {
        int d = nt * 8 + tg * 2;
        *(float2*)&O0[d] = make_float2(out[nt][0] * inv0, out[nt][1] * inv0);
        *(float2*)&O1[d] = make_float2(out[nt][2] * inv1, out[nt][3] * inv1);
    }
}

// ----------------------------------------------------------------------------
// Launch
// ----------------------------------------------------------------------------
extern "C" void kernel_launch(void* const* d_in, const int* in_sizes, int n_in,
                              void* d_out, int out_size)
{
    const float* v = (const float*)d_in[0];
    const float* k = (const float*)d_in[1];
    const float* q = (const float*)d_in[2];
    const unsigned char* mask   = (const unsigned char*)d_in[3];
    const unsigned char* semask = (const unsigned char*)d_in[4];
    const float* Wv = (const float*)d_in[5];
    const float* bv = (const float*)d_in[6];
    const float* Wk = (const float*)d_in[7];
    const float* bk = (const float*)d_in[8];
    const float* Wq = (const float*)d_in[9];
    const float* bq = (const float*)d_in[10];
    const float* Wm = (const float*)d_in[11];
    const float* bm = (const float*)d_in[12];

    static float*  Qp = nullptr;
    static float*  Cp = nullptr;
    static __half* K16p = nullptr;
    static __half* V16p = nullptr;
    if (!Qp) {
        cudaGetSymbolAddress((void**)&Qp, g_Q);
        cudaGetSymbolAddress((void**)&Cp, g_C);
        cudaGetSymbolAddress((void**)&K16p, g_K16);
        cudaGetSymbolAddress((void**)&V16p, g_V16h);
        cudaFuncSetAttribute(gemm_mma_kernel<float>,
                             cudaFuncAttributeMaxDynamicSharedMemorySize, GSMEM);
        cudaFuncSetAttribute(gemm_mma_kernel<__half>,
                             cudaFuncAttributeMaxDynamicSharedMemorySize, GSMEM);
    }

    mask_prep_kernel<<<1, 1024>>>(mask, semask);

    dim3 ggrid(DD / 128, MSZ / 128);  // (8, 32)
    gemm_mma_kernel<__half><<<ggrid, 256, GSMEM>>>(v, Wv, bv, V16p, MSZ, DD, DD);
    gemm_mma_kernel<__half><<<ggrid, 256, GSMEM>>>(k, Wk, bk, K16p, MSZ, DD, DD);
    gemm_mma_kernel<float><<<ggrid, 256, GSMEM>>>(q, Wq, bq, Qp, MSZ, DD, DD);

    vtrans_kernel<<<dim3(SS / 64, HH, BB), 256>>>();

    dim3 agrid(SS / 128, HH, BB);     // (8, 16, 4)
    attn_mma_kernel<<<agrid, 256>>>();

    gemm_mma_kernel<float><<<ggrid, 256, GSMEM>>>(Cp, Wm, bm, (float*)d_out, MSZ, DD, DD);
}

// round 17
// speedup vs baseline: 2.3586x; 1.4275x over previous
#include <cuda_runtime.h>
#include <cuda_fp16.h>
#include <math.h>

// Problem constants
#define BB 4
#define SS 1024
#define DD 1024
#define HH 16
#define DHH 64
#define MSZ (BB * SS)  // 4096 rows

// Scratch (no cudaMalloc allowed)
__device__ float  g_C[(size_t)MSZ * DD];        // attention output (fp32)
__device__ __half g_Q16[(size_t)MSZ * DD];      // Q projection, fp16
__device__ __half g_K16[(size_t)MSZ * DD];      // K projection, fp16
__device__ __half g_V16h[(size_t)MSZ * DD];     // V projection, fp16, [s][D]
__device__ __half g_V16T[(size_t)MSZ * DD];     // V transposed  [b][h][d][s]
__device__ unsigned char g_mask[BB * SS];

// ----------------------------------------------------------------------------
// Mask canonicalization (verified R4)
// ----------------------------------------------------------------------------
__global__ __launch_bounds__(1024) void mask_prep_kernel(
    const unsigned char* __restrict__ m0,
    const unsigned char* __restrict__ m1)
{
    __shared__ int s_flags;
    const int t = threadIdx.x;
    if (t == 0) s_flags = 0;
    __syncthreads();

    int f1 = 0, f23 = 0;
    for (int i = t; i < BB * SS; i += 1024) {
        unsigned char a = (unsigned char)(m0[i] | m1[i]);
        int r = i & 3;
        if (a) {
            if (r == 1) f1 = 1;
            else if (r >= 2) f23 = 1;
        }
    }
    if (f1)  atomicOr(&s_flags, 1);
    if (f23) atomicOr(&s_flags, 2);
    __syncthreads();

    const int fl = s_flags;
    int code;
    if (fl & 1)      code = 0;  // uint8
    else if (fl & 2) code = 1;  // float32
    else             code = 2;  // int32

    for (int i = t; i < BB * SS; i += 1024) {
        unsigned char mm;
        if (code == 0) {
            mm = (unsigned char)((m0[i] != 0) | (m1[i] != 0));
        } else if (code == 1) {
            mm = (unsigned char)((((const float*)m0)[i] != 0.f) |
                                 (((const float*)m1)[i] != 0.f));
        } else {
            mm = (unsigned char)((((const int*)m0)[i] != 0) |
                                 (((const int*)m1)[i] != 0));
        }
        g_mask[i] = mm;
    }
}

// ----------------------------------------------------------------------------
// Shared helpers (fp16)
// ----------------------------------------------------------------------------
__device__ __forceinline__ void mma16816(
    float& c0, float& c1, float& c2, float& c3,
    unsigned a0, unsigned a1, unsigned a2, unsigned a3,
    unsigned b0, unsigned b1)
{
    asm volatile(
        "mma.sync.aligned.m16n8k16.row.col.f32.f16.f16.f32 "
        "{%0,%1,%2,%3}, {%4,%5,%6,%7}, {%8,%9}, {%0,%1,%2,%3};\n"
        : "+f"(c0), "+f"(c1), "+f"(c2), "+f"(c3)
        : "r"(a0), "r"(a1), "r"(a2), "r"(a3), "r"(b0), "r"(b1));
}

__device__ __forceinline__ void ldsm4(unsigned addr, unsigned& r0, unsigned& r1,
                                      unsigned& r2, unsigned& r3)
{
    asm volatile(
        "ldmatrix.sync.aligned.m8n8.x4.shared.b16 {%0,%1,%2,%3}, [%4];"
        : "=r"(r0), "=r"(r1), "=r"(r2), "=r"(r3) : "r"(addr));
}

__device__ __forceinline__ void cpasync16(unsigned saddr, const void* gaddr)
{
    asm volatile("cp.async.cg.shared.global [%0], [%1], 16;\n"
                 :: "r"(saddr), "l"(gaddr));
}
#define CP_COMMIT() asm volatile("cp.async.commit_group;\n" ::: "memory")
#define CP_WAIT1()  asm volatile("cp.async.wait_group 1;\n" ::: "memory")
#define CP_WAIT0()  asm volatile("cp.async.wait_group 0;\n" ::: "memory")

__device__ __forceinline__ void split1(float x, __half& h, __half& l)
{
    h = __float2half(x);
    l = __float2half(x - __half2float(h));
}

// Pack two floats into fp16x2 register bits.
__device__ __forceinline__ unsigned pack_h2(float a, float b)
{
    __half2 h2; h2.x = __float2half(a); h2.y = __float2half(b);
    return *(unsigned*)&h2;
}

__device__ __forceinline__ void store2(float* p, float a, float b)
{
    p[0] = a; p[1] = b;
}
__device__ __forceinline__ void store2(__half* p, float a, float b)
{
    __half2 h2; h2.x = __float2half(a); h2.y = __float2half(b);
    *(__half2*)p = h2;
}

// ----------------------------------------------------------------------------
// Tensor-core GEMM: C = A @ W^T + bias.
// TP=true : 2-pass (Ah+Al)·Wh — used for the final projection (fp32 out).
// TP=false: 1-pass Ah·Wh     — used for Q/K/V projections (fp16 out).
// ----------------------------------------------------------------------------
#define SM_STRIDE 40
#define GPLANE    (128 * SM_STRIDE)
#define PLB       (GPLANE * 2)
#define GSMEM_2P  (2 * 3 * PLB)   // 61440
#define GSMEM_1P  (2 * 2 * PLB)   // 40960

template <typename OutT, bool TP>
__global__ __launch_bounds__(256, 2) void gemm_mma_kernel(
    const float* __restrict__ A, const float* __restrict__ W,
    const float* __restrict__ bias, OutT* __restrict__ C,
    int M, int N, int K)
{
    extern __shared__ __half smdyn[];
    constexpr int NPL = TP ? 3 : 2;            // planes per stage
    constexpr unsigned STAGEB = NPL * PLB;
    constexpr unsigned WOFF = (NPL - 1) * PLB; // W plane byte offset

    const int tid  = threadIdx.x;
    const int bm   = blockIdx.y * 128;
    const int bn   = blockIdx.x * 128;
    const int wid  = tid >> 5;
    const int lane = tid & 31;
    const int wm   = wid & 1;
    const int wn   = wid >> 1;
    const int g    = lane >> 2;
    const int tg   = lane & 3;

    const int lm = lane >> 3;
    const int lt = lane & 7;
    unsigned smem_u32;
    {
        unsigned long long p = __cvta_generic_to_shared(smdyn);
        smem_u32 = (unsigned)p;
    }
    const unsigned aoff = ((wm * 64 + ((lm & 1) << 3) + lt) * SM_STRIDE +
                           ((lm >> 1) << 3)) * 2;
    const unsigned boff = ((wn * 32 + ((lm >> 1) << 3) + lt) * SM_STRIDE +
                           ((lm & 1) << 3)) * 2;

    float acc[4][4][4];
#pragma unroll
    for (int mt = 0; mt < 4; mt++)
#pragma unroll
        for (int nt = 0; nt < 4; nt++)
#pragma unroll
            for (int e = 0; e < 4; e++) acc[mt][nt][e] = 0.f;

    const int srow = tid >> 3;
    const int sc4  = (tid & 7) << 2;

    float4 av[4], wv[4];
#pragma unroll
    for (int i = 0; i < 4; i++) {
        int row = srow + i * 32;
        av[i] = *(const float4*)&A[(size_t)(bm + row) * K + sc4];
        wv[i] = *(const float4*)&W[(size_t)(bn + row) * K + sc4];
    }
    {
        __half* Ahp = smdyn;
        __half* Alp = smdyn + GPLANE;               // only used if TP
        __half* Whp = smdyn + (NPL - 1) * GPLANE;
#pragma unroll
        for (int i = 0; i < 4; i++) {
            int row = srow + i * 32;
            float ax[4] = {av[i].x, av[i].y, av[i].z, av[i].w};
            float wx[4] = {wv[i].x, wv[i].y, wv[i].z, wv[i].w};
#pragma unroll
            for (int e = 0; e < 4; e++) {
                if (TP) {
                    __half h, l;
                    split1(ax[e], h, l);
                    Ahp[row * SM_STRIDE + sc4 + e] = h;
                    Alp[row * SM_STRIDE + sc4 + e] = l;
                } else {
                    Ahp[row * SM_STRIDE + sc4 + e] = __float2half(ax[e]);
                }
                Whp[row * SM_STRIDE + sc4 + e] = __float2half(wx[e]);
            }
        }
    }
    __syncthreads();

    const int NT = K / 32;
    for (int kt = 0; kt < NT; kt++) {
        const int cur = kt & 1;
        if (kt + 1 < NT) {
            int k0 = (kt + 1) * 32;
#pragma unroll
            for (int i = 0; i < 4; i++) {
                int row = srow + i * 32;
                av[i] = *(const float4*)&A[(size_t)(bm + row) * K + k0 + sc4];
                wv[i] = *(const float4*)&W[(size_t)(bn + row) * K + k0 + sc4];
            }
        }

        const unsigned sbase = smem_u32 + (unsigned)cur * STAGEB;
#pragma unroll
        for (int ks = 0; ks < 32; ks += 16) {
            unsigned bh[4][2];
#pragma unroll
            for (int p = 0; p < 2; p++) {
                unsigned ad = sbase + WOFF + boff +
                              (unsigned)(p * 16 * SM_STRIDE + ks) * 2;
                unsigned r0, r1, r2, r3;
                ldsm4(ad, r0, r1, r2, r3);
                bh[2 * p][0] = r0; bh[2 * p][1] = r1;
                bh[2 * p + 1][0] = r2; bh[2 * p + 1][1] = r3;
            }
#pragma unroll
            for (int mt = 0; mt < 4; mt++) {
                unsigned ad = sbase + aoff +
                              (unsigned)(mt * 16 * SM_STRIDE + ks) * 2;
                unsigned ah0, ah1, ah2, ah3;
                ldsm4(ad, ah0, ah1, ah2, ah3);
#pragma unroll
                for (int nt = 0; nt < 4; nt++) {
                    mma16816(acc[mt][nt][0], acc[mt][nt][1],
                             acc[mt][nt][2], acc[mt][nt][3],
                             ah0, ah1, ah2, ah3, bh[nt][0], bh[nt][1]);
                }
                if (TP) {
                    unsigned al0, al1, al2, al3;
                    ldsm4(ad + PLB, al0, al1, al2, al3);
#pragma unroll
                    for (int nt = 0; nt < 4; nt++) {
                        mma16816(acc[mt][nt][0], acc[mt][nt][1],
                                 acc[mt][nt][2], acc[mt][nt][3],
                                 al0, al1, al2, al3, bh[nt][0], bh[nt][1]);
                    }
                }
            }
        }

        if (kt + 1 < NT) {
            int nxt = cur ^ 1;
            __syncthreads();
            __half* Ahp = smdyn + nxt * NPL * GPLANE;
            __half* Alp = Ahp + GPLANE;
            __half* Whp = Ahp + (NPL - 1) * GPLANE;
#pragma unroll
            for (int i = 0; i < 4; i++) {
                int row = srow + i * 32;
                float ax[4] = {av[i].x, av[i].y, av[i].z, av[i].w};
                float wx[4] = {wv[i].x, wv[i].y, wv[i].z, wv[i].w};
#pragma unroll
                for (int e = 0; e < 4; e++) {
                    if (TP) {
                        __half h, l;
                        split1(ax[e], h, l);
                        Ahp[row * SM_STRIDE + sc4 + e] = h;
                        Alp[row * SM_STRIDE + sc4 + e] = l;
                    } else {
                        Ahp[row * SM_STRIDE + sc4 + e] = __float2half(ax[e]);
                    }
                    Whp[row * SM_STRIDE + sc4 + e] = __float2half(wx[e]);
                }
            }
            __syncthreads();
        }
    }

    // Epilogue
#pragma unroll
    for (int nt = 0; nt < 4; nt++) {
        int col = bn + wn * 32 + nt * 8 + tg * 2;
        float b0 = bias[col];
        float b1 = bias[col + 1];
#pragma unroll
        for (int mt = 0; mt < 4; mt++) {
            int row = bm + wm * 64 + mt * 16 + g;
            store2(C + (size_t)row * N + col, acc[mt][nt][0] + b0, acc[mt][nt][1] + b1);
            store2(C + (size_t)(row + 8) * N + col, acc[mt][nt][2] + b0, acc[mt][nt][3] + b1);
        }
    }
}

// ----------------------------------------------------------------------------
// V transpose: g_V16h [b*SS+s][D] -> g_V16T [b][h][d][s]  (fp16 -> fp16)
// ----------------------------------------------------------------------------
__global__ __launch_bounds__(256) void vtrans_kernel()
{
    __shared__ __half vt[64][72];
    const int tid = threadIdx.x;
    const int s0  = blockIdx.x * 64;
    const int h   = blockIdx.y;
    const int b   = blockIdx.z;

#pragma unroll
    for (int i = 0; i < 2; i++) {
        int c = tid + i * 256;           // 0..511
        int srow = c >> 3, c8 = c & 7;
        uint4 val = *(const uint4*)&g_V16h[(size_t)(b * SS + s0 + srow) * DD +
                                           h * DHH + c8 * 8];
        __half tmp[8];
        *(uint4*)tmp = val;
#pragma unroll
        for (int e = 0; e < 8; e++) vt[c8 * 8 + e][srow] = tmp[e];
    }
    __syncthreads();
#pragma unroll
    for (int i = 0; i < 2; i++) {
        int c = tid + i * 256;
        int drow = c >> 3, c8 = c & 7;
        uint4 val = *(const uint4*)&vt[drow][c8 * 8];
        *(uint4*)&g_V16T[((size_t)(b * HH + h) * DHH + drow) * SS + s0 + c8 * 8] = val;
    }
}

// ----------------------------------------------------------------------------
// Flash attention: fp16, QK 1-pass (fp16 Q), PV 1-pass.
// K/V tiles staged by cp.async (double-buffered).
// ----------------------------------------------------------------------------
#define AST 72
#define APLB (64 * AST * 2)  // 9216 B per plane

__global__ __launch_bounds__(256) void attn_mma_kernel()
{
    const int tid  = threadIdx.x;
    const int wid  = tid >> 5;
    const int lane = tid & 31;
    const int g    = lane >> 2;
    const int tg   = lane & 3;
    const int qb   = blockIdx.x * 128;
    const int h    = blockIdx.y;
    const int b    = blockIdx.z;
    const int hoff = h * DHH;
    const int qrow0 = qb + wid * 16;

    __shared__ __align__(16) __half Kh[2][64][AST];
    __shared__ __align__(16) __half Vt[2][64][AST];  // [dim][key]
    __shared__ unsigned char smask[64];

    unsigned kh_u32, vt_u32;
    {
        unsigned long long p = __cvta_generic_to_shared(&Kh[0][0][0]);
        kh_u32 = (unsigned)p;
        p = __cvta_generic_to_shared(&Vt[0][0][0]);
        vt_u32 = (unsigned)p;
    }

    // Q fragments: direct fp16 loads (no split)
    unsigned qh[4][4];
    {
        const __half* Q0 = g_Q16 + (size_t)(b * SS + qrow0 + g) * DD + hoff;
        const __half* Q1 = g_Q16 + (size_t)(b * SS + qrow0 + g + 8) * DD + hoff;
#pragma unroll
        for (int ks = 0; ks < 4; ks++) {
            int d0 = ks * 16 + tg * 2;
            qh[ks][0] = *(const unsigned*)&Q0[d0];
            qh[ks][1] = *(const unsigned*)&Q1[d0];
            qh[ks][2] = *(const unsigned*)&Q0[d0 + 8];
            qh[ks][3] = *(const unsigned*)&Q1[d0 + 8];
        }
    }

    // Staging: 2 K-chunks + 2 V-chunks (16 B each) per thread per tile.
    const int c0r = tid >> 3;
    const int c0c = (tid & 7) * 8;
    const int c1r = (tid + 256) >> 3;
    const int c1c = ((tid + 256) & 7) * 8;

    auto stage = [&](int s, int kt) {
        unsigned kb = kh_u32 + (unsigned)s * APLB;
        unsigned vb = vt_u32 + (unsigned)s * APLB;
        const __half* Ksrc = g_K16 + (size_t)(b * SS + kt * 64) * DD + hoff;
        const __half* Vsrc = g_V16T + ((size_t)(b * HH + h) * DHH) * SS + kt * 64;
        cpasync16(kb + (unsigned)(c0r * AST + c0c) * 2, Ksrc + (size_t)c0r * DD + c0c);
        cpasync16(kb + (unsigned)(c1r * AST + c1c) * 2, Ksrc + (size_t)c1r * DD + c1c);
        cpasync16(vb + (unsigned)(c0r * AST + c0c) * 2, Vsrc + (size_t)c0r * SS + c0c);
        cpasync16(vb + (unsigned)(c1r * AST + c1c) * 2, Vsrc + (size_t)c1r * SS + c1c);
    };

    float out[8][4];
#pragma unroll
    for (int nt = 0; nt < 8; nt++)
#pragma unroll
        for (int e = 0; e < 4; e++) out[nt][e] = 0.f;
    float m0 = -INFINITY, m1 = -INFINITY;
    float l0 = 0.f, l1 = 0.f;

    stage(0, 0);
    CP_COMMIT();

    const int NTK = SS / 64;  // 16
    for (int kt = 0; kt < NTK; kt++) {
        const int cur = kt & 1;
        __syncthreads();  // reads of buffer (kt+1)&1 (from tile kt-1) complete
        if (kt + 1 < NTK) {
            stage(cur ^ 1, kt + 1);
            CP_COMMIT();
            CP_WAIT1();
        } else {
            CP_WAIT0();
        }
        if (tid < 64) smask[tid] = g_mask[b * SS + kt * 64 + tid];
        __syncthreads();  // tile kt data + mask visible

        // ---- S = Q @ K^T (1-pass) ----
        float sacc[8][4];
#pragma unroll
        for (int nt = 0; nt < 8; nt++) {
#pragma unroll
            for (int e = 0; e < 4; e++) sacc[nt][e] = 0.f;
            int n = nt * 8 + g;
#pragma unroll
            for (int ks = 0; ks < 4; ks++) {
                int kc = ks * 16 + tg * 2;
                unsigned bh0 = *(const unsigned*)&Kh[cur][n][kc];
                unsigned bh1 = *(const unsigned*)&Kh[cur][n][kc + 8];
                mma16816(sacc[nt][0], sacc[nt][1], sacc[nt][2], sacc[nt][3],
                         qh[ks][0], qh[ks][1], qh[ks][2], qh[ks][3], bh0, bh1);
            }
        }

        float tmax0 = -INFINITY, tmax1 = -INFINITY;
#pragma unroll
        for (int nt = 0; nt < 8; nt++) {
            bool msk0 = smask[nt * 8 + tg * 2] != 0;
            bool msk1 = smask[nt * 8 + tg * 2 + 1] != 0;
            sacc[nt][0] = msk0 ? -1e9f : sacc[nt][0] * 0.125f;
            sacc[nt][1] = msk1 ? -1e9f : sacc[nt][1] * 0.125f;
            sacc[nt][2] = msk0 ? -1e9f : sacc[nt][2] * 0.125f;
            sacc[nt][3] = msk1 ? -1e9f : sacc[nt][3] * 0.125f;
            tmax0 = fmaxf(tmax0, fmaxf(sacc[nt][0], sacc[nt][1]));
            tmax1 = fmaxf(tmax1, fmaxf(sacc[nt][2], sacc[nt][3]));
        }
        tmax0 = fmaxf(tmax0, __shfl_xor_sync(0xffffffffu, tmax0, 1));
        tmax0 = fmaxf(tmax0, __shfl_xor_sync(0xffffffffu, tmax0, 2));
        tmax1 = fmaxf(tmax1, __shfl_xor_sync(0xffffffffu, tmax1, 1));
        tmax1 = fmaxf(tmax1, __shfl_xor_sync(0xffffffffu, tmax1, 2));

        float mn0 = fmaxf(m0, tmax0);
        float mn1 = fmaxf(m1, tmax1);
        float corr0 = __expf(m0 - mn0);
        float corr1 = __expf(m1 - mn1);
        m0 = mn0; m1 = mn1;
        l0 *= corr0; l1 *= corr1;
#pragma unroll
        for (int nt = 0; nt < 8; nt++) {
            out[nt][0] *= corr0; out[nt][1] *= corr0;
            out[nt][2] *= corr1; out[nt][3] *= corr1;
        }

        // ---- P = exp(S - m), fp16 A-fragments ----
        unsigned ph[4][4];
#pragma unroll
        for (int ksp = 0; ksp < 4; ksp++) {
            float p00 = __expf(sacc[2 * ksp][0] - m0);
            float p01 = __expf(sacc[2 * ksp][1] - m0);
            float p10 = __expf(sacc[2 * ksp][2] - m1);
            float p11 = __expf(sacc[2 * ksp][3] - m1);
            float p20 = __expf(sacc[2 * ksp + 1][0] - m0);
            float p21 = __expf(sacc[2 * ksp + 1][1] - m0);
            float p30 = __expf(sacc[2 * ksp + 1][2] - m1);
            float p31 = __expf(sacc[2 * ksp + 1][3] - m1);
            l0 += p00 + p01 + p20 + p21;
            l1 += p10 + p11 + p30 + p31;
            ph[ksp][0] = pack_h2(p00, p01);
            ph[ksp][1] = pack_h2(p10, p11);
            ph[ksp][2] = pack_h2(p20, p21);
            ph[ksp][3] = pack_h2(p30, p31);
        }

        // ---- O += P @ V (1-pass) ----
#pragma unroll
        for (int nt = 0; nt < 8; nt++) {
            int n = nt * 8 + g;
#pragma unroll
            for (int ksp = 0; ksp < 4; ksp++) {
                int kc = ksp * 16 + tg * 2;
                unsigned bh0 = *(const unsigned*)&Vt[cur][n][kc];
                unsigned bh1 = *(const unsigned*)&Vt[cur][n][kc + 8];
                mma16816(out[nt][0], out[nt][1], out[nt][2], out[nt][3],
                         ph[ksp][0], ph[ksp][1], ph[ksp][2], ph[ksp][3], bh0, bh1);
            }
        }
    }

    l0 += __shfl_xor_sync(0xffffffffu, l0, 1);
    l0 += __shfl_xor_sync(0xffffffffu, l0, 2);
    l1 += __shfl_xor_sync(0xffffffffu, l1, 1);
    l1 += __shfl_xor_sync(0xffffffffu, l1, 2);
    const float inv0 = 1.f / l0;
    const float inv1 = 1.f / l1;

    float* O0 = g_C + (size_t)(b * SS + qrow0 + g) * DD + hoff;
    float* O1 = g_C + (size_t)(b * SS + qrow0 + g + 8) * DD + hoff;
#pragma unroll
    for (int nt = 0; nt < 8; nt++) {
        int d = nt * 8 + tg * 2;
        *(float2*)&O0[d] = make_float2(out[nt][0] * inv0, out[nt][1] * inv0);
        *(float2*)&O1[d] = make_float2(out[nt][2] * inv1, out[nt][3] * inv1);
    }
}

// ----------------------------------------------------------------------------
// Launch
// ----------------------------------------------------------------------------
extern "C" void kernel_launch(void* const* d_in, const int* in_sizes, int n_in,
                              void* d_out, int out_size)
{
    const float* v = (const float*)d_in[0];
    const float* k = (const float*)d_in[1];
    const float* q = (const float*)d_in[2];
    const unsigned char* mask   = (const unsigned char*)d_in[3];
    const unsigned char* semask = (const unsigned char*)d_in[4];
    const float* Wv = (const float*)d_in[5];
    const float* bv = (const float*)d_in[6];
    const float* Wk = (const float*)d_in[7];
    const float* bk = (const float*)d_in[8];
    const float* Wq = (const float*)d_in[9];
    const float* bq = (const float*)d_in[10];
    const float* Wm = (const float*)d_in[11];
    const float* bm = (const float*)d_in[12];

    static float*  Cp = nullptr;
    static __half* Q16p = nullptr;
    static __half* K16p = nullptr;
    static __half* V16p = nullptr;
    if (!Cp) {
        cudaGetSymbolAddress((void**)&Cp, g_C);
        cudaGetSymbolAddress((void**)&Q16p, g_Q16);
        cudaGetSymbolAddress((void**)&K16p, g_K16);
        cudaGetSymbolAddress((void**)&V16p, g_V16h);
        cudaFuncSetAttribute((gemm_mma_kernel<float, true>),
                             cudaFuncAttributeMaxDynamicSharedMemorySize, GSMEM_2P);
        cudaFuncSetAttribute((gemm_mma_kernel<__half, false>),
                             cudaFuncAttributeMaxDynamicSharedMemorySize, GSMEM_1P);
    }

    mask_prep_kernel<<<1, 1024>>>(mask, semask);

    dim3 ggrid(DD / 128, MSZ / 128);  // (8, 32)
    gemm_mma_kernel<__half, false><<<ggrid, 256, GSMEM_1P>>>(v, Wv, bv, V16p, MSZ, DD, DD);
    gemm_mma_kernel<__half, false><<<ggrid, 256, GSMEM_1P>>>(k, Wk, bk, K16p, MSZ, DD, DD);
    gemm_mma_kernel<__half, false><<<ggrid, 256, GSMEM_1P>>>(q, Wq, bq, Q16p, MSZ, DD, DD);

    vtrans_kernel<<<dim3(SS / 64, HH, BB), 256>>>();

    dim3 agrid(SS / 128, HH, BB);     // (8, 16, 4)
    attn_mma_kernel<<<agrid, 256>>>();

    gemm_mma_kernel<float, true><<<ggrid, 256, GSMEM_2P>>>(Cp, Wm, bm, (float*)d_out, MSZ, DD, DD);
}